// round 2
// baseline (speedup 1.0000x reference)
#include <cuda_runtime.h>
#include <cstddef>

// ---------------- problem constants ----------------
#define DD0 41
#define DD1 20          // (41-3)/2+1
#define DD2 9           // (20-3)/2+1
#define HH  200
#define WW  176
#define HWs 35200
#define EPSV 1e-3f

#define N0MAX 30016
#define N1MAX 60032     // <= 2*N0
#define N2MAX 120064    // <= 2*M1
#define TCAP  65536     // per-tap pair capacity (>= N1MAX? no: >= M1 max 60000) OK

#define MAP0_SZ (2*DD0*HWs)   // 2,886,400
#define MAP1_SZ (2*DD1*HWs)   // 1,408,000
#define MAP2_SZ (2*DD2*HWs)   //   633,600
#define OUT_TOTAL (2*64*DD2*HWs)

// ---------------- device scratch ----------------
__device__ __align__(16) int   g_map0[MAP0_SZ];
__device__ __align__(16) int   g_map1[MAP1_SZ];
__device__ __align__(16) int   g_map2[MAP2_SZ];

__device__ __align__(16) float g_Y0[(size_t)N0MAX*64];
__device__ __align__(16) float g_Z1[(size_t)N1MAX*64];
__device__ __align__(16) float g_YA[(size_t)N1MAX*64];
__device__ __align__(16) float g_YB[(size_t)N1MAX*64];
__device__ __align__(16) float g_Z2[(size_t)N2MAX*64];

__device__ __align__(16) int4  g_c1[N1MAX];
__device__ __align__(16) int4  g_c2[N2MAX];

__device__ __align__(16) int2  g_p0[27*TCAP];
__device__ __align__(16) int2  g_p1[27*TCAP];
__device__ int   g_pc0[27];
__device__ int   g_pc1[27];
__device__ int   g_cnt[4];          // [0]=N0  [1]=M1  [2]=M2
__device__ float g_stats[5*128];    // per BN layer: 64 sums + 64 sumsqs

// ---------------- init ----------------
__global__ void k_init(int n0) {
    int tid = blockIdx.x*blockDim.x + threadIdx.x;
    int stride = gridDim.x*blockDim.x;
    int4 z4 = make_int4(0,0,0,0);
    int4* m0 = (int4*)g_map0;
    for (int i = tid; i < MAP0_SZ/4; i += stride) m0[i] = z4;
    int4* m1 = (int4*)g_map1;
    for (int i = tid; i < MAP1_SZ/4; i += stride) m1[i] = z4;
    int4* m2 = (int4*)g_map2;
    for (int i = tid; i < MAP2_SZ/4; i += stride) m2[i] = z4;
    if (tid < 27) { g_pc0[tid] = 0; g_pc1[tid] = 0; }
    if (tid < 5*128) g_stats[tid] = 0.0f;
    if (tid == 0) { g_cnt[0] = n0; g_cnt[1] = 0; g_cnt[2] = 0; g_cnt[3] = 0; }
}

// ---------------- map build / pair build ----------------
__global__ void k_map0(const int4* __restrict__ coors, int n0) {
    int i = blockIdx.x*256 + threadIdx.x;
    if (i >= n0) return;
    int4 c = coors[i];
    g_map0[((c.x*DD0 + c.y)*HH + c.z)*WW + c.w] = i + 1;
}

__global__ void k_build0(const int4* __restrict__ coors, int n0) {
    int i = blockIdx.x*256 + threadIdx.x;
    if (i >= n0) return;
    int4 c = coors[i];
    int b = c.x, z = c.y, y = c.z, x = c.w;
    #pragma unroll
    for (int dz = -1; dz <= 1; dz++)
    #pragma unroll
    for (int dy = -1; dy <= 1; dy++)
    #pragma unroll
    for (int dx = -1; dx <= 1; dx++) {
        int t = (dz+1)*9 + (dy+1)*3 + (dx+1);
        if (t == 13) continue;
        int nz = z+dz, ny = y+dy, nx = x+dx;
        if (nz < 0 || nz >= DD0 || ny < 0 || ny >= HH || nx < 0 || nx >= WW) continue;
        int j = g_map0[((b*DD0 + nz)*HH + ny)*WW + nx] - 1;
        if (j >= 0) {
            int pos = atomicAdd(&g_pc0[t], 1);
            g_p0[t*TCAP + pos] = make_int2(j, i);
        }
    }
    #pragma unroll
    for (int kz = 0; kz < 3; kz++) {
        int tt = z - kz;
        if (tt >= 0 && (tt & 1) == 0) {
            int oz = tt >> 1;
            if (oz < DD1) g_map1[((b*DD1 + oz)*HH + y)*WW + x] = 1;
        }
    }
}

__global__ void k_build1() {
    int r = blockIdx.x*256 + threadIdx.x;
    if (r >= g_cnt[1]) return;
    int4 c = g_c1[r];
    int b = c.x, z = c.y, y = c.z, x = c.w;
    #pragma unroll
    for (int dz = -1; dz <= 1; dz++)
    #pragma unroll
    for (int dy = -1; dy <= 1; dy++)
    #pragma unroll
    for (int dx = -1; dx <= 1; dx++) {
        int t = (dz+1)*9 + (dy+1)*3 + (dx+1);
        if (t == 13) continue;
        int nz = z+dz, ny = y+dy, nx = x+dx;
        if (nz < 0 || nz >= DD1 || ny < 0 || ny >= HH || nx < 0 || nx >= WW) continue;
        int j = g_map1[((b*DD1 + nz)*HH + ny)*WW + nx] - 2;
        if (j >= 0) {
            int pos = atomicAdd(&g_pc1[t], 1);
            g_p1[t*TCAP + pos] = make_int2(j, r);
        }
    }
    #pragma unroll
    for (int kz = 0; kz < 3; kz++) {
        int tt = z - kz;
        if (tt >= 0 && (tt & 1) == 0) {
            int oz = tt >> 1;
            if (oz < DD2) g_map2[((b*DD2 + oz)*HH + y)*WW + x] = 1;
        }
    }
}

// ---------------- compact marked map -> row ids + coords ----------------
__global__ void k_compact(int which) {
    int* map   = which ? g_map2 : g_map1;
    int size4  = which ? MAP2_SZ/4 : MAP1_SZ/4;
    int D      = which ? DD2 : DD1;
    int4* cout = which ? g_c2 : g_c1;
    int ci     = which ? 2 : 1;
    __shared__ int scnt, sbase;
    int gid = blockIdx.x*256 + threadIdx.x;
    if (threadIdx.x == 0) scnt = 0;
    __syncthreads();
    bool in = gid < size4;
    int4 v = make_int4(0,0,0,0);
    if (in) v = ((int4*)map)[gid];
    int vals[4] = {v.x, v.y, v.z, v.w};
    int my = (vals[0]==1) + (vals[1]==1) + (vals[2]==1) + (vals[3]==1);
    int loc = 0;
    if (my) loc = atomicAdd(&scnt, my);
    __syncthreads();
    if (threadIdx.x == 0) sbase = scnt ? atomicAdd(&g_cnt[ci], scnt) : 0;
    __syncthreads();
    if (!in) return;
    if (my) {
        int idx = sbase + loc;
        int lin = gid*4;
        int outv[4];
        #pragma unroll
        for (int q = 0; q < 4; q++) {
            if (vals[q] == 1) {
                int L = lin + q;
                int b = L / (D*HWs);
                int r = L % (D*HWs);
                int z = r / HWs;
                int rr = r % HWs;
                int y = rr / WW;
                int x = rr % WW;
                cout[idx] = make_int4(b, z, y, x);
                outv[q] = idx + 2;
                idx++;
            } else outv[q] = 0;
        }
        ((int4*)map)[gid] = make_int4(outv[0], outv[1], outv[2], outv[3]);
    }
}

// ---------------- tiled conv kernels ----------------
// MODE 0: center (rows 0..cnt, identity src, plain store)
// MODE 1: per-tap pair list (grid.y = tap), atomicAdd into Y
// MODE 2: z-gather K=192 (3 taps concatenated), plain store
template<int K, int MODE>
__global__ void k_conv(const float* __restrict__ X, const float* __restrict__ Wsrc,
                       float* __restrict__ Y, int ci, int sel) {
    extern __shared__ float sm[];
    float* sW = sm;             // K*64
    float* sF = sm + K*64;      // K*12 (transposed, rows padded to 12)
    __shared__ int sj[24];

    const int2* pairs = nullptr; const int* pcnt = nullptr;
    const int4* ocoords = nullptr; const int* inmap = nullptr;
    int inD = 0, bias = 0;
    if (MODE == 1) { pairs = sel ? g_p1 : g_p0; pcnt = sel ? g_pc1 : g_pc0; }
    if (MODE == 2) {
        if (sel) { ocoords = g_c2; inmap = g_map1; inD = DD1; bias = 2; }
        else     { ocoords = g_c1; inmap = g_map0; inD = DD0; bias = 1; }
    }

    const float* Wp = Wsrc + (MODE == 1 ? (size_t)blockIdx.y*(K*64) : 0);
    for (int i = threadIdx.x; i < K*16; i += 128)
        ((float4*)sW)[i] = ((const float4*)Wp)[i];

    int total = (MODE == 1) ? pcnt[blockIdx.y] : g_cnt[ci];

    for (int base = blockIdx.x*8; base < total; base += gridDim.x*8) {
        int nr = min(8, total - base);
        __syncthreads();    // prev compute done; sW load done on first iter
        if (MODE == 2) {
            if (threadIdx.x < 24) {
                int p = threadIdx.x / 3, seg = threadIdx.x % 3;
                int j = -1;
                if (p < nr) {
                    int4 c = ocoords[base + p];
                    int zi = c.y*2 + seg;
                    if (zi < inD) j = inmap[((c.x*inD + zi)*HH + c.z)*WW + c.w] - bias;
                }
                sj[threadIdx.x] = j;
            }
            __syncthreads();
            // stage: 8 rows x 192 floats -> sF[k][p], pad 12
            for (int i = threadIdx.x; i < 8*48; i += 128) {
                int p = i / 48, q = i % 48;
                int seg = q / 16, qq = q % 16;
                int j = sj[p*3 + seg];
                float4 v = make_float4(0.f,0.f,0.f,0.f);
                if (j >= 0) v = ((const float4*)X)[(size_t)j*16 + qq];
                int k0 = seg*64 + qq*4;
                sF[(k0+0)*12 + p] = v.x;
                sF[(k0+1)*12 + p] = v.y;
                sF[(k0+2)*12 + p] = v.z;
                sF[(k0+3)*12 + p] = v.w;
            }
        } else {
            const int RQ = K/4;
            for (int i = threadIdx.x; i < 8*RQ; i += 128) {
                int p = i / RQ, q = i % RQ;
                float4 v = make_float4(0.f,0.f,0.f,0.f);
                if (p < nr) {
                    int row = (MODE == 0) ? (base + p)
                                          : pairs[(size_t)blockIdx.y*TCAP + base + p].x;
                    v = ((const float4*)X)[(size_t)row*RQ + q];
                }
                int k0 = q*4;
                sF[(k0+0)*12 + p] = v.x;
                sF[(k0+1)*12 + p] = v.y;
                sF[(k0+2)*12 + p] = v.z;
                sF[(k0+3)*12 + p] = v.w;
            }
        }
        __syncthreads();

        int c = threadIdx.x & 63;
        int h = threadIdx.x >> 6;           // 0..1, rows h*4..h*4+3
        float a0 = 0.f, a1 = 0.f, a2 = 0.f, a3 = 0.f;
        #pragma unroll 8
        for (int k = 0; k < K; k++) {
            float w = sW[k*64 + c];
            float4 f = *reinterpret_cast<const float4*>(sF + k*12 + h*4);
            a0 += f.x * w; a1 += f.y * w; a2 += f.z * w; a3 += f.w * w;
        }
        int p0 = h*4;
        if (MODE == 1) {
            const int2* pb = pairs + (size_t)blockIdx.y*TCAP + base;
            if (p0+0 < nr) atomicAdd(&Y[(size_t)pb[p0+0].y*64 + c], a0);
            if (p0+1 < nr) atomicAdd(&Y[(size_t)pb[p0+1].y*64 + c], a1);
            if (p0+2 < nr) atomicAdd(&Y[(size_t)pb[p0+2].y*64 + c], a2);
            if (p0+3 < nr) atomicAdd(&Y[(size_t)pb[p0+3].y*64 + c], a3);
        } else {
            if (p0+0 < nr) Y[(size_t)(base+p0+0)*64 + c] = a0;
            if (p0+1 < nr) Y[(size_t)(base+p0+1)*64 + c] = a1;
            if (p0+2 < nr) Y[(size_t)(base+p0+2)*64 + c] = a2;
            if (p0+3 < nr) Y[(size_t)(base+p0+3)*64 + c] = a3;
        }
    }
}

// ---------------- BN ----------------
__global__ void k_stats(const float* __restrict__ X, int ci, int layer) {
    __shared__ float ss[512];
    int cnt = g_cnt[ci];
    int c = threadIdx.x & 63, g = threadIdx.x >> 6;
    float s = 0.f, q = 0.f;
    for (int r = blockIdx.x*4 + g; r < cnt; r += gridDim.x*4) {
        float v = X[(size_t)r*64 + c];
        s += v; q += v*v;
    }
    ss[threadIdx.x] = s; ss[256 + threadIdx.x] = q;
    __syncthreads();
    if (threadIdx.x < 64) {
        s = ss[threadIdx.x] + ss[threadIdx.x+64] + ss[threadIdx.x+128] + ss[threadIdx.x+192];
        q = ss[256+threadIdx.x] + ss[320+threadIdx.x] + ss[384+threadIdx.x] + ss[448+threadIdx.x];
        atomicAdd(&g_stats[layer*128 + threadIdx.x], s);
        atomicAdd(&g_stats[layer*128 + 64 + threadIdx.x], q);
    }
}

__global__ void k_apply(float* __restrict__ X, int ci, int layer,
                        const float* __restrict__ gm, const float* __restrict__ bt) {
    int cnt = g_cnt[ci];
    long total = (long)cnt * 64;
    float cn = fmaxf((float)cnt, 1.0f);
    for (long e = (long)blockIdx.x*blockDim.x + threadIdx.x; e < total;
         e += (long)gridDim.x*blockDim.x) {
        int c = (int)(e & 63);
        float mean = g_stats[layer*128 + c] / cn;
        float var  = g_stats[layer*128 + 64 + c] / cn - mean*mean;
        float inv  = rsqrtf(var + EPSV);
        float v = X[e];
        float y = gm[c] * (v - mean) * inv + bt[c];
        X[e] = fmaxf(y, 0.0f);
    }
}

// ---------------- final: BN + ReLU + dense scatter (fused) ----------------
__global__ void k_out(const float* __restrict__ Z2, float* __restrict__ out,
                      const float* __restrict__ gm, const float* __restrict__ bt) {
    int cnt = g_cnt[2];
    float cn = fmaxf((float)cnt, 1.0f);
    const int tot4 = OUT_TOTAL/4;
    for (int e4 = blockIdx.x*blockDim.x + threadIdx.x; e4 < tot4;
         e4 += gridDim.x*blockDim.x) {
        int e = e4 * 4;
        int x  = e % WW;
        int t1 = e / WW;
        int y  = t1 % HH;
        int t2 = t1 / HH;
        int cz = t2 % (64*DD2);
        int b  = t2 / (64*DD2);
        int c  = cz / DD2;
        int z  = cz - c*DD2;
        float mean = g_stats[512 + c] / cn;
        float var  = g_stats[512 + 64 + c] / cn - mean*mean;
        float inv  = rsqrtf(var + EPSV);
        float ga = gm[c], be = bt[c];
        int midx = ((b*DD2 + z)*HH + y)*WW + x;
        int4 m = *reinterpret_cast<const int4*>(g_map2 + midx);
        float4 o;
        int j;
        j = m.x - 2; o.x = (j >= 0) ? fmaxf(ga*(Z2[(size_t)j*64 + c] - mean)*inv + be, 0.f) : 0.f;
        j = m.y - 2; o.y = (j >= 0) ? fmaxf(ga*(Z2[(size_t)j*64 + c] - mean)*inv + be, 0.f) : 0.f;
        j = m.z - 2; o.z = (j >= 0) ? fmaxf(ga*(Z2[(size_t)j*64 + c] - mean)*inv + be, 0.f) : 0.f;
        j = m.w - 2; o.w = (j >= 0) ? fmaxf(ga*(Z2[(size_t)j*64 + c] - mean)*inv + be, 0.f) : 0.f;
        ((float4*)out)[e4] = o;
    }
}

// ---------------- launch ----------------
extern "C" void kernel_launch(void* const* d_in, const int* in_sizes, int n_in,
                              void* d_out, int out_size) {
    const float* vox   = (const float*)d_in[0];
    const int4*  coors = (const int4*) d_in[1];
    const float* w0    = (const float*)d_in[3];
    const float* gg0   = (const float*)d_in[4];
    const float* bb0   = (const float*)d_in[5];
    const float* ws1   = (const float*)d_in[6];
    const float* ggs1  = (const float*)d_in[7];
    const float* bbs1  = (const float*)d_in[8];
    const float* w1a   = (const float*)d_in[9];
    const float* gg1a  = (const float*)d_in[10];
    const float* bb1a  = (const float*)d_in[11];
    const float* w1b   = (const float*)d_in[12];
    const float* gg1b  = (const float*)d_in[13];
    const float* bb1b  = (const float*)d_in[14];
    const float* ws2   = (const float*)d_in[15];
    const float* ggs2  = (const float*)d_in[16];
    const float* bbs2  = (const float*)d_in[17];
    float* out = (float*)d_out;
    int n0 = in_sizes[0] / 128;

    void *pY0, *pZ1, *pYA, *pYB, *pZ2;
    cudaGetSymbolAddress(&pY0, g_Y0);
    cudaGetSymbolAddress(&pZ1, g_Z1);
    cudaGetSymbolAddress(&pYA, g_YA);
    cudaGetSymbolAddress(&pYB, g_YB);
    cudaGetSymbolAddress(&pZ2, g_Z2);
    float* Y0 = (float*)pY0; float* Z1 = (float*)pZ1;
    float* YA = (float*)pYA; float* YB = (float*)pYB; float* Z2 = (float*)pZ2;

    cudaFuncSetAttribute(k_conv<192,2>, cudaFuncAttributeMaxDynamicSharedMemorySize, 192*304);

    int gb0 = (n0 + 255) / 256;

    k_init<<<1024, 256>>>(n0);
    k_map0<<<gb0, 256>>>(coors, n0);
    k_build0<<<gb0, 256>>>(coors, n0);

    // stage 0: subm 128->64
    k_conv<128,0><<<1480, 128, 128*304>>>(vox, w0 + 13*128*64, Y0, 0, 0);
    k_conv<128,1><<<dim3(96,27), 128, 128*304>>>(vox, w0, Y0, 0, 0);
    k_stats<<<256, 256>>>(Y0, 0, 0);
    k_apply<<<512, 256>>>(Y0, 0, 0, gg0, bb0);

    // stride-z conv 1
    k_compact<<<MAP1_SZ/4/256, 256>>>(0);
    k_conv<192,2><<<1184, 128, 192*304>>>(Y0, ws1, Z1, 1, 0);
    k_stats<<<256, 256>>>(Z1, 1, 1);
    k_apply<<<512, 256>>>(Z1, 1, 1, ggs1, bbs1);

    // subm pair build for stage 1 (shared by both subm layers)
    k_build1<<<(N1MAX+255)/256, 256>>>();

    // subm1a
    k_conv<64,0><<<1480, 128, 64*304>>>(Z1, w1a + 13*64*64, YA, 1, 0);
    k_conv<64,1><<<dim3(96,27), 128, 64*304>>>(Z1, w1a, YA, 1, 1);
    k_stats<<<256, 256>>>(YA, 1, 2);
    k_apply<<<512, 256>>>(YA, 1, 2, gg1a, bb1a);

    // subm1b
    k_conv<64,0><<<1480, 128, 64*304>>>(YA, w1b + 13*64*64, YB, 1, 0);
    k_conv<64,1><<<dim3(96,27), 128, 64*304>>>(YA, w1b, YB, 1, 1);
    k_stats<<<256, 256>>>(YB, 1, 3);
    k_apply<<<512, 256>>>(YB, 1, 3, gg1b, bb1b);

    // stride-z conv 2
    k_compact<<<(MAP2_SZ/4 + 255)/256, 256>>>(1);
    k_conv<192,2><<<1184, 128, 192*304>>>(YB, ws2, Z2, 2, 1);
    k_stats<<<256, 256>>>(Z2, 2, 4);

    // fused BN+ReLU+dense scatter
    k_out<<<2368, 256>>>(Z2, out, ggs2, bbs2);

    (void)n_in; (void)out_size;
}

// round 3
// speedup vs baseline: 1.0431x; 1.0431x over previous
#include <cuda_runtime.h>
#include <cstddef>

// ---------------- problem constants ----------------
#define DD0 41
#define DD1 20          // (41-3)/2+1
#define DD2 9           // (20-3)/2+1
#define HH  200
#define WW  176
#define HWs 35200
#define EPSV 1e-3f

#define N0MAX 30016
#define N1MAX 60032     // <= 2*N0
#define N2MAX 120064    // <= 2*M1
#define TCAP  65536     // per-tap pair capacity

#define MAP0_SZ (2*DD0*HWs)   // 2,886,400
#define MAP1_SZ (2*DD1*HWs)   // 1,408,000
#define MAP2_SZ (2*DD2*HWs)   //   633,600
#define OUT_TOTAL (2*64*DD2*HWs)

// ---------------- device scratch ----------------
__device__ __align__(16) int   g_map0[MAP0_SZ];
__device__ __align__(16) int   g_map1[MAP1_SZ];
__device__ __align__(16) int   g_map2[MAP2_SZ];

__device__ __align__(16) float g_Y0[(size_t)N0MAX*64];
__device__ __align__(16) float g_Z1[(size_t)N1MAX*64];
__device__ __align__(16) float g_YA[(size_t)N1MAX*64];
__device__ __align__(16) float g_YB[(size_t)N1MAX*64];
__device__ __align__(16) float g_Z2[(size_t)N2MAX*64];

__device__ __align__(16) int4  g_c1[N1MAX];
__device__ __align__(16) int4  g_c2[N2MAX];

__device__ __align__(16) int2  g_p0[27*TCAP];
__device__ __align__(16) int2  g_p1[27*TCAP];
__device__ int   g_pc0[27];
__device__ int   g_pc1[27];
__device__ int   g_cnt[4];          // [0]=N0  [1]=M1  [2]=M2
__device__ float g_stats[5*128];    // per BN layer: 64 sums + 64 sumsqs

// ---------------- init ----------------
__global__ void k_init(int n0) {
    int tid = blockIdx.x*blockDim.x + threadIdx.x;
    int stride = gridDim.x*blockDim.x;
    int4 z4 = make_int4(0,0,0,0);
    int4* m0 = (int4*)g_map0;
    for (int i = tid; i < MAP0_SZ/4; i += stride) m0[i] = z4;
    int4* m1 = (int4*)g_map1;
    for (int i = tid; i < MAP1_SZ/4; i += stride) m1[i] = z4;
    int4* m2 = (int4*)g_map2;
    for (int i = tid; i < MAP2_SZ/4; i += stride) m2[i] = z4;
    if (tid < 27) { g_pc0[tid] = 0; g_pc1[tid] = 0; }
    if (tid < 5*128) g_stats[tid] = 0.0f;
    if (tid == 0) { g_cnt[0] = n0; g_cnt[1] = 0; g_cnt[2] = 0; g_cnt[3] = 0; }
}

// ---------------- map build / pair build ----------------
__global__ void k_map0(const int4* __restrict__ coors, int n0) {
    int i = blockIdx.x*256 + threadIdx.x;
    if (i >= n0) return;
    int4 c = coors[i];
    g_map0[((c.x*DD0 + c.y)*HH + c.z)*WW + c.w] = i + 1;
}

__global__ void k_build0(const int4* __restrict__ coors, int n0) {
    int i = blockIdx.x*256 + threadIdx.x;
    if (i >= n0) return;
    int4 c = coors[i];
    int b = c.x, z = c.y, y = c.z, x = c.w;
    #pragma unroll
    for (int dz = -1; dz <= 1; dz++)
    #pragma unroll
    for (int dy = -1; dy <= 1; dy++)
    #pragma unroll
    for (int dx = -1; dx <= 1; dx++) {
        int t = (dz+1)*9 + (dy+1)*3 + (dx+1);
        if (t == 13) continue;
        int nz = z+dz, ny = y+dy, nx = x+dx;
        if (nz < 0 || nz >= DD0 || ny < 0 || ny >= HH || nx < 0 || nx >= WW) continue;
        int j = g_map0[((b*DD0 + nz)*HH + ny)*WW + nx] - 1;
        if (j >= 0) {
            int pos = atomicAdd(&g_pc0[t], 1);
            g_p0[t*TCAP + pos] = make_int2(j, i);
        }
    }
    #pragma unroll
    for (int kz = 0; kz < 3; kz++) {
        int tt = z - kz;
        if (tt >= 0 && (tt & 1) == 0) {
            int oz = tt >> 1;
            if (oz < DD1) g_map1[((b*DD1 + oz)*HH + y)*WW + x] = 1;
        }
    }
}

__global__ void k_build1() {
    int r = blockIdx.x*256 + threadIdx.x;
    if (r >= g_cnt[1]) return;
    int4 c = g_c1[r];
    int b = c.x, z = c.y, y = c.z, x = c.w;
    #pragma unroll
    for (int dz = -1; dz <= 1; dz++)
    #pragma unroll
    for (int dy = -1; dy <= 1; dy++)
    #pragma unroll
    for (int dx = -1; dx <= 1; dx++) {
        int t = (dz+1)*9 + (dy+1)*3 + (dx+1);
        if (t == 13) continue;
        int nz = z+dz, ny = y+dy, nx = x+dx;
        if (nz < 0 || nz >= DD1 || ny < 0 || ny >= HH || nx < 0 || nx >= WW) continue;
        int j = g_map1[((b*DD1 + nz)*HH + ny)*WW + nx] - 2;
        if (j >= 0) {
            int pos = atomicAdd(&g_pc1[t], 1);
            g_p1[t*TCAP + pos] = make_int2(j, r);
        }
    }
    #pragma unroll
    for (int kz = 0; kz < 3; kz++) {
        int tt = z - kz;
        if (tt >= 0 && (tt & 1) == 0) {
            int oz = tt >> 1;
            if (oz < DD2) g_map2[((b*DD2 + oz)*HH + y)*WW + x] = 1;
        }
    }
}

// ---------------- compact marked map -> row ids + coords ----------------
__global__ void k_compact(int which) {
    int* map   = which ? g_map2 : g_map1;
    int size4  = which ? MAP2_SZ/4 : MAP1_SZ/4;
    int D      = which ? DD2 : DD1;
    int4* cout = which ? g_c2 : g_c1;
    int ci     = which ? 2 : 1;
    __shared__ int scnt, sbase;
    int gid = blockIdx.x*256 + threadIdx.x;
    if (threadIdx.x == 0) scnt = 0;
    __syncthreads();
    bool in = gid < size4;
    int4 v = make_int4(0,0,0,0);
    if (in) v = ((int4*)map)[gid];
    int vals[4] = {v.x, v.y, v.z, v.w};
    int my = (vals[0]==1) + (vals[1]==1) + (vals[2]==1) + (vals[3]==1);
    int loc = 0;
    if (my) loc = atomicAdd(&scnt, my);
    __syncthreads();
    if (threadIdx.x == 0) sbase = scnt ? atomicAdd(&g_cnt[ci], scnt) : 0;
    __syncthreads();
    if (!in) return;
    if (my) {
        int idx = sbase + loc;
        int lin = gid*4;
        int outv[4];
        #pragma unroll
        for (int q = 0; q < 4; q++) {
            if (vals[q] == 1) {
                int L = lin + q;
                int b = L / (D*HWs);
                int r = L % (D*HWs);
                int z = r / HWs;
                int rr = r % HWs;
                int y = rr / WW;
                int x = rr % WW;
                cout[idx] = make_int4(b, z, y, x);
                outv[q] = idx + 2;
                idx++;
            } else outv[q] = 0;
        }
        ((int4*)map)[gid] = make_int4(outv[0], outv[1], outv[2], outv[3]);
    }
}

// ---------------- tiled conv kernels ----------------
// MODE 0: center tap (identity pair list, plain store)
// MODE 1: per-tap pair list (grid.y = tap), atomicAdd into Y
// MODE 2: stride-2-z gather, K=192 (3 taps concatenated), plain store
// Tile: 32 rows x 64 channels per block of 128 threads.
// Thread (cq, rg): 4 channels (cq*4..+3) x 4 rows (rg*4..+3) register tile.
#define ROWPAD 36
template<int K, int MODE>
__global__ __launch_bounds__(128) void k_conv(const float* __restrict__ X,
        const float* __restrict__ Wsrc, float* __restrict__ Y, int ci, int sel) {
    extern __shared__ float sm[];
    float* sW = sm;               // K*64 floats
    float* sF = sm + K*64;        // K*ROWPAD floats, layout [k][row]
    __shared__ int sj[96];

    const int2* pairs = nullptr;
    const int4* ocoords = nullptr; const int* inmap = nullptr;
    int inD = 0, bias = 0;
    int total;
    if (MODE == 1) {
        pairs = (sel ? g_p1 : g_p0) + (size_t)blockIdx.y*TCAP;
        total = (sel ? g_pc1 : g_pc0)[blockIdx.y];
    } else {
        total = g_cnt[ci];
    }
    if (MODE == 2) {
        if (sel) { ocoords = g_c2; inmap = g_map1; inD = DD1; bias = 2; }
        else     { ocoords = g_c1; inmap = g_map0; inD = DD0; bias = 1; }
    }
    if ((int)blockIdx.x * 32 >= total) return;   // idle block: skip weight load

    const float* Wp = Wsrc + (MODE == 1 ? (size_t)blockIdx.y*(K*64) : 0);
    for (int i = threadIdx.x; i < K*16; i += 128)
        ((float4*)sW)[i] = ((const float4*)Wp)[i];

    const float4* Xv = (const float4*)X;
    const int cq = threadIdx.x & 15;
    const int rg = threadIdx.x >> 4;

    for (int base = blockIdx.x*32; base < total; base += gridDim.x*32) {
        int nr = min(32, total - base);
        __syncthreads();   // sW ready (iter 0) / prev compute done
        if (MODE == 2) {
            if (threadIdx.x < 96) {
                int p = threadIdx.x & 31, s = threadIdx.x >> 5;
                int j = -1;
                if (p < nr) {
                    int4 c = ocoords[base + p];
                    int zi = c.y*2 + s;
                    if (zi < inD) j = inmap[((c.x*inD + zi)*HH + c.z)*WW + c.w] - bias;
                }
                sj[s*32 + p] = j;
            }
            __syncthreads();
            #pragma unroll 4
            for (int i = threadIdx.x; i < 32*48; i += 128) {
                int p = i & 31, q = i >> 5;
                int s = q >> 4, qq = q & 15;
                int j = sj[s*32 + p];
                float4 v = make_float4(0.f,0.f,0.f,0.f);
                if (j >= 0) v = Xv[(size_t)j*16 + qq];
                float* d = sF + (q*4)*ROWPAD + p;
                d[0] = v.x; d[ROWPAD] = v.y; d[2*ROWPAD] = v.z; d[3*ROWPAD] = v.w;
            }
        } else {
            const int RQ = K/4;
            #pragma unroll 4
            for (int i = threadIdx.x; i < 32*RQ; i += 128) {
                int p = i & 31, q = i >> 5;
                float4 v = make_float4(0.f,0.f,0.f,0.f);
                if (p < nr) {
                    int row = (MODE == 0) ? (base + p) : pairs[base + p].x;
                    v = Xv[(size_t)row*RQ + q];
                }
                float* d = sF + (q*4)*ROWPAD + p;
                d[0] = v.x; d[ROWPAD] = v.y; d[2*ROWPAD] = v.z; d[3*ROWPAD] = v.w;
            }
        }
        __syncthreads();

        float4 acc0 = make_float4(0.f,0.f,0.f,0.f);
        float4 acc1 = acc0, acc2 = acc0, acc3 = acc0;
        const float4* wv = (const float4*)sW;
        #pragma unroll 4
        for (int k = 0; k < K; k++) {
            float4 w = wv[k*16 + cq];
            float4 f = *(const float4*)(sF + k*ROWPAD + rg*4);
            acc0.x += f.x*w.x; acc0.y += f.x*w.y; acc0.z += f.x*w.z; acc0.w += f.x*w.w;
            acc1.x += f.y*w.x; acc1.y += f.y*w.y; acc1.z += f.y*w.z; acc1.w += f.y*w.w;
            acc2.x += f.z*w.x; acc2.y += f.z*w.y; acc2.z += f.z*w.z; acc2.w += f.z*w.w;
            acc3.x += f.w*w.x; acc3.y += f.w*w.y; acc3.z += f.w*w.z; acc3.w += f.w*w.w;
        }
        int p0 = rg*4;
        if (MODE == 1) {
            #pragma unroll
            for (int r = 0; r < 4; r++) {
                if (p0 + r < nr) {
                    float4 a = (r==0)?acc0:(r==1)?acc1:(r==2)?acc2:acc3;
                    int dst = pairs[base + p0 + r].y;
                    float* yp = Y + (size_t)dst*64 + cq*4;
                    atomicAdd(yp+0, a.x); atomicAdd(yp+1, a.y);
                    atomicAdd(yp+2, a.z); atomicAdd(yp+3, a.w);
                }
            }
        } else {
            #pragma unroll
            for (int r = 0; r < 4; r++) {
                if (p0 + r < nr) {
                    float4 a = (r==0)?acc0:(r==1)?acc1:(r==2)?acc2:acc3;
                    ((float4*)Y)[(size_t)(base + p0 + r)*16 + cq] = a;
                }
            }
        }
    }
}

// ---------------- BN ----------------
__global__ void k_stats(const float* __restrict__ X, int ci, int layer) {
    __shared__ float ss[512];
    int cnt = g_cnt[ci];
    int c = threadIdx.x & 63, g = threadIdx.x >> 6;
    float s = 0.f, q = 0.f;
    for (int r = blockIdx.x*4 + g; r < cnt; r += gridDim.x*4) {
        float v = X[(size_t)r*64 + c];
        s += v; q += v*v;
    }
    ss[threadIdx.x] = s; ss[256 + threadIdx.x] = q;
    __syncthreads();
    if (threadIdx.x < 64) {
        s = ss[threadIdx.x] + ss[threadIdx.x+64] + ss[threadIdx.x+128] + ss[threadIdx.x+192];
        q = ss[256+threadIdx.x] + ss[320+threadIdx.x] + ss[384+threadIdx.x] + ss[448+threadIdx.x];
        atomicAdd(&g_stats[layer*128 + threadIdx.x], s);
        atomicAdd(&g_stats[layer*128 + 64 + threadIdx.x], q);
    }
}

__global__ void k_apply(float* __restrict__ X, int ci, int layer,
                        const float* __restrict__ gm, const float* __restrict__ bt) {
    int cnt = g_cnt[ci];
    long total = (long)cnt * 64;
    float cn = fmaxf((float)cnt, 1.0f);
    for (long e = (long)blockIdx.x*blockDim.x + threadIdx.x; e < total;
         e += (long)gridDim.x*blockDim.x) {
        int c = (int)(e & 63);
        float mean = g_stats[layer*128 + c] / cn;
        float var  = g_stats[layer*128 + 64 + c] / cn - mean*mean;
        float inv  = rsqrtf(var + EPSV);
        float v = X[e];
        float y = gm[c] * (v - mean) * inv + bt[c];
        X[e] = fmaxf(y, 0.0f);
    }
}

// ---------------- final: BN + ReLU + dense scatter (fused) ----------------
__global__ void k_out(const float* __restrict__ Z2, float* __restrict__ out,
                      const float* __restrict__ gm, const float* __restrict__ bt) {
    int cnt = g_cnt[2];
    float cn = fmaxf((float)cnt, 1.0f);
    const int tot4 = OUT_TOTAL/4;
    for (int e4 = blockIdx.x*blockDim.x + threadIdx.x; e4 < tot4;
         e4 += gridDim.x*blockDim.x) {
        int e = e4 * 4;
        int x  = e % WW;
        int t1 = e / WW;
        int y  = t1 % HH;
        int t2 = t1 / HH;
        int cz = t2 % (64*DD2);
        int b  = t2 / (64*DD2);
        int c  = cz / DD2;
        int z  = cz - c*DD2;
        float mean = g_stats[512 + c] / cn;
        float var  = g_stats[512 + 64 + c] / cn - mean*mean;
        float inv  = rsqrtf(var + EPSV);
        float ga = gm[c], be = bt[c];
        int midx = ((b*DD2 + z)*HH + y)*WW + x;
        int4 m = *reinterpret_cast<const int4*>(g_map2 + midx);
        float4 o;
        int j;
        j = m.x - 2; o.x = (j >= 0) ? fmaxf(ga*(Z2[(size_t)j*64 + c] - mean)*inv + be, 0.f) : 0.f;
        j = m.y - 2; o.y = (j >= 0) ? fmaxf(ga*(Z2[(size_t)j*64 + c] - mean)*inv + be, 0.f) : 0.f;
        j = m.z - 2; o.z = (j >= 0) ? fmaxf(ga*(Z2[(size_t)j*64 + c] - mean)*inv + be, 0.f) : 0.f;
        j = m.w - 2; o.w = (j >= 0) ? fmaxf(ga*(Z2[(size_t)j*64 + c] - mean)*inv + be, 0.f) : 0.f;
        ((float4*)out)[e4] = o;
    }
}

// ---------------- launch ----------------
extern "C" void kernel_launch(void* const* d_in, const int* in_sizes, int n_in,
                              void* d_out, int out_size) {
    const float* vox   = (const float*)d_in[0];
    const int4*  coors = (const int4*) d_in[1];
    const float* w0    = (const float*)d_in[3];
    const float* gg0   = (const float*)d_in[4];
    const float* bb0   = (const float*)d_in[5];
    const float* ws1   = (const float*)d_in[6];
    const float* ggs1  = (const float*)d_in[7];
    const float* bbs1  = (const float*)d_in[8];
    const float* w1a   = (const float*)d_in[9];
    const float* gg1a  = (const float*)d_in[10];
    const float* bb1a  = (const float*)d_in[11];
    const float* w1b   = (const float*)d_in[12];
    const float* gg1b  = (const float*)d_in[13];
    const float* bb1b  = (const float*)d_in[14];
    const float* ws2   = (const float*)d_in[15];
    const float* ggs2  = (const float*)d_in[16];
    const float* bbs2  = (const float*)d_in[17];
    float* out = (float*)d_out;
    int n0 = in_sizes[0] / 128;

    void *pY0, *pZ1, *pYA, *pYB, *pZ2;
    cudaGetSymbolAddress(&pY0, g_Y0);
    cudaGetSymbolAddress(&pZ1, g_Z1);
    cudaGetSymbolAddress(&pYA, g_YA);
    cudaGetSymbolAddress(&pYB, g_YB);
    cudaGetSymbolAddress(&pZ2, g_Z2);
    float* Y0 = (float*)pY0; float* Z1 = (float*)pZ1;
    float* YA = (float*)pYA; float* YB = (float*)pYB; float* Z2 = (float*)pZ2;

    // dynamic smem = K*(64+ROWPAD)*4 = K*400 bytes
    cudaFuncSetAttribute(k_conv<128,0>, cudaFuncAttributeMaxDynamicSharedMemorySize, 128*400);
    cudaFuncSetAttribute(k_conv<128,1>, cudaFuncAttributeMaxDynamicSharedMemorySize, 128*400);
    cudaFuncSetAttribute(k_conv<64,0>,  cudaFuncAttributeMaxDynamicSharedMemorySize, 64*400);
    cudaFuncSetAttribute(k_conv<64,1>,  cudaFuncAttributeMaxDynamicSharedMemorySize, 64*400);
    cudaFuncSetAttribute(k_conv<192,2>, cudaFuncAttributeMaxDynamicSharedMemorySize, 192*400);

    int gb0 = (n0 + 255) / 256;

    k_init<<<1024, 256>>>(n0);
    k_map0<<<gb0, 256>>>(coors, n0);
    k_build0<<<gb0, 256>>>(coors, n0);

    // stage 0: subm 128->64
    k_conv<128,0><<<940, 128, 128*400>>>(vox, w0 + 13*128*64, Y0, 0, 0);
    k_conv<128,1><<<dim3(24,27), 128, 128*400>>>(vox, w0, Y0, 0, 0);
    k_stats<<<256, 256>>>(Y0, 0, 0);
    k_apply<<<512, 256>>>(Y0, 0, 0, gg0, bb0);

    // stride-z conv 1  (K=192 gather GEMM)
    k_compact<<<MAP1_SZ/4/256, 256>>>(0);
    k_conv<192,2><<<1480, 128, 192*400>>>(Y0, ws1, Z1, 1, 0);
    k_stats<<<256, 256>>>(Z1, 1, 1);
    k_apply<<<512, 256>>>(Z1, 1, 1, ggs1, bbs1);

    // subm pair build for stage 1 (shared by both subm layers)
    k_build1<<<(N1MAX+255)/256, 256>>>();

    // subm1a
    k_conv<64,0><<<1880, 128, 64*400>>>(Z1, w1a + 13*64*64, YA, 1, 0);
    k_conv<64,1><<<dim3(24,27), 128, 64*400>>>(Z1, w1a, YA, 1, 1);
    k_stats<<<256, 256>>>(YA, 1, 2);
    k_apply<<<512, 256>>>(YA, 1, 2, gg1a, bb1a);

    // subm1b
    k_conv<64,0><<<1880, 128, 64*400>>>(YA, w1b + 13*64*64, YB, 1, 0);
    k_conv<64,1><<<dim3(24,27), 128, 64*400>>>(YA, w1b, YB, 1, 1);
    k_stats<<<256, 256>>>(YB, 1, 3);
    k_apply<<<512, 256>>>(YB, 1, 3, gg1b, bb1b);

    // stride-z conv 2  (K=192 gather GEMM)
    k_compact<<<(MAP2_SZ/4 + 255)/256, 256>>>(1);
    k_conv<192,2><<<2000, 128, 192*400>>>(YB, ws2, Z2, 2, 1);
    k_stats<<<256, 256>>>(Z2, 2, 4);

    // fused BN+ReLU+dense scatter
    k_out<<<2368, 256>>>(Z2, out, ggs2, bbs2);

    (void)n_in; (void)out_size;
}

// round 4
// speedup vs baseline: 1.1161x; 1.0700x over previous
#include <cuda_runtime.h>
#include <cstddef>

// ---------------- problem constants ----------------
#define DD0 41
#define DD1 20          // (41-3)/2+1
#define DD2 9           // (20-3)/2+1
#define HH  200
#define WW  176
#define HWs 35200
#define EPSV 1e-3f

#define N0MAX 30016
#define N1MAX 60032     // <= 2*N0
#define N2MAX 120064    // <= 2*M1
#define TCAP  65536     // per-tap pair capacity

#define MAP0_SZ (2*DD0*HWs)   // 2,886,400
#define MAP1_SZ (2*DD1*HWs)   // 1,408,000
#define MAP2_SZ (2*DD2*HWs)   //   633,600
#define OUT_TOTAL (2*64*DD2*HWs)

// ---------------- device scratch ----------------
__device__ __align__(16) int   g_map0[MAP0_SZ];
__device__ __align__(16) int   g_map1[MAP1_SZ];
__device__ __align__(16) int   g_map2[MAP2_SZ];

__device__ __align__(16) float g_Y0[(size_t)N0MAX*64];
__device__ __align__(16) float g_Z1[(size_t)N1MAX*64];
__device__ __align__(16) float g_YA[(size_t)N1MAX*64];
__device__ __align__(16) float g_YB[(size_t)N1MAX*64];
__device__ __align__(16) float g_Z2[(size_t)N2MAX*64];

__device__ __align__(16) int4  g_c1[N1MAX];
__device__ __align__(16) int4  g_c2[N2MAX];

__device__ __align__(16) int2  g_p0[27*TCAP];
__device__ __align__(16) int2  g_p1[27*TCAP];
__device__ int   g_pc0[27];
__device__ int   g_pc1[27];
__device__ int   g_cnt[4];          // [0]=N0  [1]=M1  [2]=M2
__device__ float g_stats[5*128];    // per BN layer: 64 sums + 64 sumsqs

// ---------------- init ----------------
__global__ void k_init(int n0) {
    int tid = blockIdx.x*blockDim.x + threadIdx.x;
    int stride = gridDim.x*blockDim.x;
    int4 z4 = make_int4(0,0,0,0);
    int4* m0 = (int4*)g_map0;
    for (int i = tid; i < MAP0_SZ/4; i += stride) m0[i] = z4;
    int4* m1 = (int4*)g_map1;
    for (int i = tid; i < MAP1_SZ/4; i += stride) m1[i] = z4;
    int4* m2 = (int4*)g_map2;
    for (int i = tid; i < MAP2_SZ/4; i += stride) m2[i] = z4;
    if (tid < 27) { g_pc0[tid] = 0; g_pc1[tid] = 0; }
    if (tid < 5*128) g_stats[tid] = 0.0f;
    if (tid == 0) { g_cnt[0] = n0; g_cnt[1] = 0; g_cnt[2] = 0; g_cnt[3] = 0; }
}

// ---------------- map build / pair build ----------------
__global__ void k_map0(const int4* __restrict__ coors, int n0) {
    int i = blockIdx.x*256 + threadIdx.x;
    if (i >= n0) return;
    int4 c = coors[i];
    g_map0[((c.x*DD0 + c.y)*HH + c.z)*WW + c.w] = i + 1;
}

__global__ void k_build0(const int4* __restrict__ coors, int n0) {
    int i = blockIdx.x*256 + threadIdx.x;
    if (i >= n0) return;
    int4 c = coors[i];
    int b = c.x, z = c.y, y = c.z, x = c.w;
    #pragma unroll
    for (int dz = -1; dz <= 1; dz++)
    #pragma unroll
    for (int dy = -1; dy <= 1; dy++)
    #pragma unroll
    for (int dx = -1; dx <= 1; dx++) {
        int t = (dz+1)*9 + (dy+1)*3 + (dx+1);
        if (t == 13) continue;
        int nz = z+dz, ny = y+dy, nx = x+dx;
        if (nz < 0 || nz >= DD0 || ny < 0 || ny >= HH || nx < 0 || nx >= WW) continue;
        int j = g_map0[((b*DD0 + nz)*HH + ny)*WW + nx] - 1;
        if (j >= 0) {
            int pos = atomicAdd(&g_pc0[t], 1);
            g_p0[t*TCAP + pos] = make_int2(j, i);
        }
    }
    #pragma unroll
    for (int kz = 0; kz < 3; kz++) {
        int tt = z - kz;
        if (tt >= 0 && (tt & 1) == 0) {
            int oz = tt >> 1;
            if (oz < DD1) g_map1[((b*DD1 + oz)*HH + y)*WW + x] = 1;
        }
    }
}

__global__ void k_build1() {
    int r = blockIdx.x*256 + threadIdx.x;
    if (r >= g_cnt[1]) return;
    int4 c = g_c1[r];
    int b = c.x, z = c.y, y = c.z, x = c.w;
    #pragma unroll
    for (int dz = -1; dz <= 1; dz++)
    #pragma unroll
    for (int dy = -1; dy <= 1; dy++)
    #pragma unroll
    for (int dx = -1; dx <= 1; dx++) {
        int t = (dz+1)*9 + (dy+1)*3 + (dx+1);
        if (t == 13) continue;
        int nz = z+dz, ny = y+dy, nx = x+dx;
        if (nz < 0 || nz >= DD1 || ny < 0 || ny >= HH || nx < 0 || nx >= WW) continue;
        int j = g_map1[((b*DD1 + nz)*HH + ny)*WW + nx] - 2;
        if (j >= 0) {
            int pos = atomicAdd(&g_pc1[t], 1);
            g_p1[t*TCAP + pos] = make_int2(j, r);
        }
    }
    #pragma unroll
    for (int kz = 0; kz < 3; kz++) {
        int tt = z - kz;
        if (tt >= 0 && (tt & 1) == 0) {
            int oz = tt >> 1;
            if (oz < DD2) g_map2[((b*DD2 + oz)*HH + y)*WW + x] = 1;
        }
    }
}

// ---------------- compact marked map -> row ids + coords ----------------
__global__ void k_compact(int which) {
    int* map   = which ? g_map2 : g_map1;
    int size4  = which ? MAP2_SZ/4 : MAP1_SZ/4;
    int D      = which ? DD2 : DD1;
    int4* cout = which ? g_c2 : g_c1;
    int ci     = which ? 2 : 1;
    __shared__ int scnt, sbase;
    int gid = blockIdx.x*256 + threadIdx.x;
    if (threadIdx.x == 0) scnt = 0;
    __syncthreads();
    bool in = gid < size4;
    int4 v = make_int4(0,0,0,0);
    if (in) v = ((int4*)map)[gid];
    int vals[4] = {v.x, v.y, v.z, v.w};
    int my = (vals[0]==1) + (vals[1]==1) + (vals[2]==1) + (vals[3]==1);
    int loc = 0;
    if (my) loc = atomicAdd(&scnt, my);
    __syncthreads();
    if (threadIdx.x == 0) sbase = scnt ? atomicAdd(&g_cnt[ci], scnt) : 0;
    __syncthreads();
    if (!in) return;
    if (my) {
        int idx = sbase + loc;
        int lin = gid*4;
        int outv[4];
        #pragma unroll
        for (int q = 0; q < 4; q++) {
            if (vals[q] == 1) {
                int L = lin + q;
                int b = L / (D*HWs);
                int r = L % (D*HWs);
                int z = r / HWs;
                int rr = r % HWs;
                int y = rr / WW;
                int x = rr % WW;
                cout[idx] = make_int4(b, z, y, x);
                outv[q] = idx + 2;
                idx++;
            } else outv[q] = 0;
        }
        ((int4*)map)[gid] = make_int4(outv[0], outv[1], outv[2], outv[3]);
    }
}

// ---------------- tiled conv kernels ----------------
// MODE 0: center tap (identity row list, plain store)
// MODE 1: per-tap pair list (grid.y = tap), atomicAdd into Y
// MODE 2: stride-2-z gather, K=192 (3 taps concat), plain store + fused BN stats
// Tile: 32 rows x 64 channels per block of 128 threads.
// Staging: thread t owns row p=t&31, float4-range [g*NQ4,(g+1)*NQ4), g=t>>5.
// Register-prefetch pipeline: gather LDGs for tile i+1 issued before compute(i).
#define ROWPAD 36
template<int K, int MODE>
__global__ __launch_bounds__(128) void k_conv(const float* __restrict__ X,
        const float* __restrict__ Wsrc, float* __restrict__ Y, int ci, int sel,
        int layer) {
    extern __shared__ float sm[];
    float* sW = sm;               // K*64 floats
    float* sF = sm + K*64;        // K*ROWPAD floats, layout [k][row]
    __shared__ float sred[512];

    constexpr int NQ4 = K/16;     // float4s staged per thread

    const int2* pairs = nullptr;
    const int4* ocoords = nullptr; const int* inmap = nullptr;
    int inD = 0, bias = 0;
    int total;
    if (MODE == 1) {
        pairs = (sel ? g_p1 : g_p0) + (size_t)blockIdx.y*TCAP;
        total = (sel ? g_pc1 : g_pc0)[blockIdx.y];
    } else {
        total = g_cnt[ci];
    }
    if (MODE == 2) {
        if (sel) { ocoords = g_c2; inmap = g_map1; inD = DD1; bias = 2; }
        else     { ocoords = g_c1; inmap = g_map0; inD = DD0; bias = 1; }
    }
    if ((int)blockIdx.x * 32 >= total) return;   // idle block

    const float* Wp = Wsrc + (MODE == 1 ? (size_t)blockIdx.y*(K*64) : 0);
    for (int i = threadIdx.x; i < K*16; i += 128)
        ((float4*)sW)[i] = ((const float4*)Wp)[i];

    const float4* Xv = (const float4*)X;
    const int p  = threadIdx.x & 31;   // staging row
    const int g  = threadIdx.x >> 5;   // staging quarter
    const int cq = threadIdx.x & 15;   // compute: channel quad
    const int rg = threadIdx.x >> 4;   // compute: row group

    const int gstride = gridDim.x * 32;

    float4 st[NQ4];

    // ---- prefetch lambda: gather rows of tile at 'pb' into st[] ----
    auto prefetch = [&](int pb) {
        if (pb >= total) return;
        int pnr = total - pb; if (pnr > 32) pnr = 32;
        if (p >= pnr) {
            #pragma unroll
            for (int qi = 0; qi < NQ4; qi++) st[qi] = make_float4(0.f,0.f,0.f,0.f);
            return;
        }
        if (MODE == 2) {
            int4 c = ocoords[pb + p];
            const int s0 = (g*NQ4) >> 4;
            const int s1 = (g*NQ4 + NQ4 - 1) >> 4;
            int j0 = -1, j1 = -1;
            {
                int zi = c.y*2 + s0;
                if (zi < inD) j0 = inmap[((c.x*inD + zi)*HH + c.z)*WW + c.w] - bias;
            }
            if (s1 != s0) {
                int zi = c.y*2 + s1;
                if (zi < inD) j1 = inmap[((c.x*inD + zi)*HH + c.z)*WW + c.w] - bias;
            } else j1 = j0;
            #pragma unroll
            for (int qi = 0; qi < NQ4; qi++) {
                int q4 = g*NQ4 + qi;
                int j = ((q4 >> 4) == s0) ? j0 : j1;
                st[qi] = (j >= 0) ? Xv[(size_t)j*16 + (q4 & 15)]
                                  : make_float4(0.f,0.f,0.f,0.f);
            }
        } else {
            int row = (MODE == 0) ? (pb + p) : pairs[pb + p].x;
            const float4* xp = Xv + (size_t)row*(K/4) + g*NQ4;
            #pragma unroll
            for (int qi = 0; qi < NQ4; qi++) st[qi] = xp[qi];
        }
    };

    float4 sacc = make_float4(0.f,0.f,0.f,0.f);   // BN sums (MODE2)
    float4 qacc = make_float4(0.f,0.f,0.f,0.f);   // BN sumsqs

    prefetch(blockIdx.x*32);

    for (int base = blockIdx.x*32; base < total; base += gstride) {
        int nr = min(32, total - base);
        __syncthreads();    // sF free (prev compute done) / sW ready (iter 0)
        // store staged regs -> sF transposed [k][row]
        #pragma unroll
        for (int qi = 0; qi < NQ4; qi++) {
            int q4 = g*NQ4 + qi;
            float* d = sF + (q4*4)*ROWPAD + p;
            d[0] = st[qi].x; d[ROWPAD] = st[qi].y;
            d[2*ROWPAD] = st[qi].z; d[3*ROWPAD] = st[qi].w;
        }
        __syncthreads();
        prefetch(base + gstride);     // LDGs in flight during compute

        float4 a0 = make_float4(0.f,0.f,0.f,0.f);
        float4 a1 = a0, a2 = a0, a3 = a0;
        const float4* wv = (const float4*)sW;
        float4 wA = wv[cq];
        float4 fA = *(const float4*)(sF + rg*4);
        #pragma unroll 8
        for (int k = 0; k < K; k++) {
            float4 wB, fB;
            if (k < K-1) {
                wB = wv[(k+1)*16 + cq];
                fB = *(const float4*)(sF + (k+1)*ROWPAD + rg*4);
            }
            a0.x += fA.x*wA.x; a0.y += fA.x*wA.y; a0.z += fA.x*wA.z; a0.w += fA.x*wA.w;
            a1.x += fA.y*wA.x; a1.y += fA.y*wA.y; a1.z += fA.y*wA.z; a1.w += fA.y*wA.w;
            a2.x += fA.z*wA.x; a2.y += fA.z*wA.y; a2.z += fA.z*wA.z; a2.w += fA.z*wA.w;
            a3.x += fA.w*wA.x; a3.y += fA.w*wA.y; a3.z += fA.w*wA.z; a3.w += fA.w*wA.w;
            wA = wB; fA = fB;
        }
        int p0 = rg*4;
        if (MODE == 1) {
            #pragma unroll
            for (int r = 0; r < 4; r++) {
                if (p0 + r < nr) {
                    float4 a = (r==0)?a0:(r==1)?a1:(r==2)?a2:a3;
                    int dst = pairs[base + p0 + r].y;
                    float* yp = Y + (size_t)dst*64 + cq*4;
                    atomicAdd(yp+0, a.x); atomicAdd(yp+1, a.y);
                    atomicAdd(yp+2, a.z); atomicAdd(yp+3, a.w);
                }
            }
        } else {
            #pragma unroll
            for (int r = 0; r < 4; r++) {
                if (p0 + r < nr) {
                    float4 a = (r==0)?a0:(r==1)?a1:(r==2)?a2:a3;
                    ((float4*)Y)[(size_t)(base + p0 + r)*16 + cq] = a;
                }
            }
        }
        if (MODE == 2) {   // invalid rows have acc==0: contribute nothing
            sacc.x += a0.x+a1.x+a2.x+a3.x;
            sacc.y += a0.y+a1.y+a2.y+a3.y;
            sacc.z += a0.z+a1.z+a2.z+a3.z;
            sacc.w += a0.w+a1.w+a2.w+a3.w;
            qacc.x += a0.x*a0.x+a1.x*a1.x+a2.x*a2.x+a3.x*a3.x;
            qacc.y += a0.y*a0.y+a1.y*a1.y+a2.y*a2.y+a3.y*a3.y;
            qacc.z += a0.z*a0.z+a1.z*a1.z+a2.z*a2.z+a3.z*a3.z;
            qacc.w += a0.w*a0.w+a1.w*a1.w+a2.w*a2.w+a3.w*a3.w;
        }
    }

    if (MODE == 2) {       // fused BN stats: block-reduce then atomic
        sacc.x += __shfl_xor_sync(0xffffffffu, sacc.x, 16);
        sacc.y += __shfl_xor_sync(0xffffffffu, sacc.y, 16);
        sacc.z += __shfl_xor_sync(0xffffffffu, sacc.z, 16);
        sacc.w += __shfl_xor_sync(0xffffffffu, sacc.w, 16);
        qacc.x += __shfl_xor_sync(0xffffffffu, qacc.x, 16);
        qacc.y += __shfl_xor_sync(0xffffffffu, qacc.y, 16);
        qacc.z += __shfl_xor_sync(0xffffffffu, qacc.z, 16);
        qacc.w += __shfl_xor_sync(0xffffffffu, qacc.w, 16);
        int lane = threadIdx.x & 31, warp = threadIdx.x >> 5;
        if (lane < 16) {
            float* rs = sred + warp*64 + lane*4;
            rs[0] = sacc.x; rs[1] = sacc.y; rs[2] = sacc.z; rs[3] = sacc.w;
            float* rq = sred + 256 + warp*64 + lane*4;
            rq[0] = qacc.x; rq[1] = qacc.y; rq[2] = qacc.z; rq[3] = qacc.w;
        }
        __syncthreads();
        if (threadIdx.x < 64) {
            int t = threadIdx.x;
            float s = sred[t] + sred[64+t] + sred[128+t] + sred[192+t];
            float q = sred[256+t] + sred[320+t] + sred[384+t] + sred[448+t];
            atomicAdd(&g_stats[layer*128 + t], s);
            atomicAdd(&g_stats[layer*128 + 64 + t], q);
        }
    }
}

// ---------------- BN ----------------
__global__ void k_stats(const float* __restrict__ X, int ci, int layer) {
    __shared__ float ss[512];
    int cnt = g_cnt[ci];
    int c = threadIdx.x & 63, g = threadIdx.x >> 6;
    float s = 0.f, q = 0.f;
    for (int r = blockIdx.x*4 + g; r < cnt; r += gridDim.x*4) {
        float v = X[(size_t)r*64 + c];
        s += v; q += v*v;
    }
    ss[threadIdx.x] = s; ss[256 + threadIdx.x] = q;
    __syncthreads();
    if (threadIdx.x < 64) {
        s = ss[threadIdx.x] + ss[threadIdx.x+64] + ss[threadIdx.x+128] + ss[threadIdx.x+192];
        q = ss[256+threadIdx.x] + ss[320+threadIdx.x] + ss[384+threadIdx.x] + ss[448+threadIdx.x];
        atomicAdd(&g_stats[layer*128 + threadIdx.x], s);
        atomicAdd(&g_stats[layer*128 + 64 + threadIdx.x], q);
    }
}

__global__ void k_apply(float* __restrict__ X, int ci, int layer,
                        const float* __restrict__ gm, const float* __restrict__ bt) {
    int cnt = g_cnt[ci];
    long total = (long)cnt * 64;
    float cn = fmaxf((float)cnt, 1.0f);
    for (long e = (long)blockIdx.x*blockDim.x + threadIdx.x; e < total;
         e += (long)gridDim.x*blockDim.x) {
        int c = (int)(e & 63);
        float mean = g_stats[layer*128 + c] / cn;
        float var  = g_stats[layer*128 + 64 + c] / cn - mean*mean;
        float inv  = rsqrtf(var + EPSV);
        float v = X[e];
        float y = gm[c] * (v - mean) * inv + bt[c];
        X[e] = fmaxf(y, 0.0f);
    }
}

// ---------------- final: BN + ReLU + dense scatter (fused) ----------------
__global__ void k_out(const float* __restrict__ Z2, float* __restrict__ out,
                      const float* __restrict__ gm, const float* __restrict__ bt) {
    int cnt = g_cnt[2];
    float cn = fmaxf((float)cnt, 1.0f);
    const int tot4 = OUT_TOTAL/4;
    for (int e4 = blockIdx.x*blockDim.x + threadIdx.x; e4 < tot4;
         e4 += gridDim.x*blockDim.x) {
        int e = e4 * 4;
        int x  = e % WW;
        int t1 = e / WW;
        int y  = t1 % HH;
        int t2 = t1 / HH;
        int cz = t2 % (64*DD2);
        int b  = t2 / (64*DD2);
        int c  = cz / DD2;
        int z  = cz - c*DD2;
        float mean = g_stats[512 + c] / cn;
        float var  = g_stats[512 + 64 + c] / cn - mean*mean;
        float inv  = rsqrtf(var + EPSV);
        float ga = gm[c], be = bt[c];
        int midx = ((b*DD2 + z)*HH + y)*WW + x;
        int4 m = *reinterpret_cast<const int4*>(g_map2 + midx);
        float4 o;
        int j;
        j = m.x - 2; o.x = (j >= 0) ? fmaxf(ga*(Z2[(size_t)j*64 + c] - mean)*inv + be, 0.f) : 0.f;
        j = m.y - 2; o.y = (j >= 0) ? fmaxf(ga*(Z2[(size_t)j*64 + c] - mean)*inv + be, 0.f) : 0.f;
        j = m.z - 2; o.z = (j >= 0) ? fmaxf(ga*(Z2[(size_t)j*64 + c] - mean)*inv + be, 0.f) : 0.f;
        j = m.w - 2; o.w = (j >= 0) ? fmaxf(ga*(Z2[(size_t)j*64 + c] - mean)*inv + be, 0.f) : 0.f;
        ((float4*)out)[e4] = o;
    }
}

// ---------------- launch ----------------
extern "C" void kernel_launch(void* const* d_in, const int* in_sizes, int n_in,
                              void* d_out, int out_size) {
    const float* vox   = (const float*)d_in[0];
    const int4*  coors = (const int4*) d_in[1];
    const float* w0    = (const float*)d_in[3];
    const float* gg0   = (const float*)d_in[4];
    const float* bb0   = (const float*)d_in[5];
    const float* ws1   = (const float*)d_in[6];
    const float* ggs1  = (const float*)d_in[7];
    const float* bbs1  = (const float*)d_in[8];
    const float* w1a   = (const float*)d_in[9];
    const float* gg1a  = (const float*)d_in[10];
    const float* bb1a  = (const float*)d_in[11];
    const float* w1b   = (const float*)d_in[12];
    const float* gg1b  = (const float*)d_in[13];
    const float* bb1b  = (const float*)d_in[14];
    const float* ws2   = (const float*)d_in[15];
    const float* ggs2  = (const float*)d_in[16];
    const float* bbs2  = (const float*)d_in[17];
    float* out = (float*)d_out;
    int n0 = in_sizes[0] / 128;

    void *pY0, *pZ1, *pYA, *pYB, *pZ2;
    cudaGetSymbolAddress(&pY0, g_Y0);
    cudaGetSymbolAddress(&pZ1, g_Z1);
    cudaGetSymbolAddress(&pYA, g_YA);
    cudaGetSymbolAddress(&pYB, g_YB);
    cudaGetSymbolAddress(&pZ2, g_Z2);
    float* Y0 = (float*)pY0; float* Z1 = (float*)pZ1;
    float* YA = (float*)pYA; float* YB = (float*)pYB; float* Z2 = (float*)pZ2;

    // dynamic smem = K*(64+ROWPAD)*4 = K*400 bytes
    cudaFuncSetAttribute(k_conv<128,0>, cudaFuncAttributeMaxDynamicSharedMemorySize, 128*400);
    cudaFuncSetAttribute(k_conv<128,1>, cudaFuncAttributeMaxDynamicSharedMemorySize, 128*400);
    cudaFuncSetAttribute(k_conv<64,0>,  cudaFuncAttributeMaxDynamicSharedMemorySize, 64*400);
    cudaFuncSetAttribute(k_conv<64,1>,  cudaFuncAttributeMaxDynamicSharedMemorySize, 64*400);
    cudaFuncSetAttribute(k_conv<192,2>, cudaFuncAttributeMaxDynamicSharedMemorySize, 192*400);

    int gb0 = (n0 + 255) / 256;

    k_init<<<1024, 256>>>(n0);
    k_map0<<<gb0, 256>>>(coors, n0);
    k_build0<<<gb0, 256>>>(coors, n0);

    // stage 0: subm 128->64
    k_conv<128,0><<<592, 128, 128*400>>>(vox, w0 + 13*128*64, Y0, 0, 0, -1);
    k_conv<128,1><<<dim3(8,27), 128, 128*400>>>(vox, w0, Y0, 0, 0, -1);
    k_stats<<<256, 256>>>(Y0, 0, 0);
    k_apply<<<512, 256>>>(Y0, 0, 0, gg0, bb0);

    // stride-z conv 1  (K=192 gather GEMM, fused BN stats -> layer 1)
    k_compact<<<MAP1_SZ/4/256, 256>>>(0);
    k_conv<192,2><<<592, 128, 192*400>>>(Y0, ws1, Z1, 1, 0, 1);
    k_apply<<<512, 256>>>(Z1, 1, 1, ggs1, bbs1);

    // subm pair build for stage 1 (shared by both subm layers)
    k_build1<<<(N1MAX+255)/256, 256>>>();

    // subm1a
    k_conv<64,0><<<592, 128, 64*400>>>(Z1, w1a + 13*64*64, YA, 1, 0, -1);
    k_conv<64,1><<<dim3(16,27), 128, 64*400>>>(Z1, w1a, YA, 1, 1, -1);
    k_stats<<<256, 256>>>(YA, 1, 2);
    k_apply<<<512, 256>>>(YA, 1, 2, gg1a, bb1a);

    // subm1b
    k_conv<64,0><<<592, 128, 64*400>>>(YA, w1b + 13*64*64, YB, 1, 0, -1);
    k_conv<64,1><<<dim3(16,27), 128, 64*400>>>(YA, w1b, YB, 1, 1, -1);
    k_stats<<<256, 256>>>(YB, 1, 3);
    k_apply<<<512, 256>>>(YB, 1, 3, gg1b, bb1b);

    // stride-z conv 2  (K=192 gather GEMM, fused BN stats -> layer 4)
    k_compact<<<(MAP2_SZ/4 + 255)/256, 256>>>(1);
    k_conv<192,2><<<592, 128, 192*400>>>(YB, ws2, Z2, 2, 1, 4);

    // fused BN+ReLU+dense scatter (uses layer-4 stats)
    k_out<<<2368, 256>>>(Z2, out, ggs2, bbs2);

    (void)n_in; (void)out_size;
}

// round 5
// speedup vs baseline: 1.2041x; 1.0788x over previous
#include <cuda_runtime.h>
#include <cstddef>

// ---------------- problem constants ----------------
#define DD0 41
#define DD1 20          // (41-3)/2+1
#define DD2 9           // (20-3)/2+1
#define HH  200
#define WW  176
#define HWs 35200
#define EPSV 1e-3f

#define N0MAX 30016
#define N1MAX 60032     // <= 2*N0
#define N2MAX 120064    // <= 2*M1
#define TCAP  65536     // per-tap pair capacity (>= max pairs per tap, proven)

#define MAP0_SZ (2*DD0*HWs)   // 2,886,400
#define MAP1_SZ (2*DD1*HWs)   // 1,408,000
#define MAP2_SZ (2*DD2*HWs)   //   633,600
#define OUT_TOTAL (2*64*DD2*HWs)

// ---------------- device scratch ----------------
__device__ __align__(16) int   g_map0[MAP0_SZ];
__device__ __align__(16) int   g_map1[MAP1_SZ];
__device__ __align__(16) int   g_map2[MAP2_SZ];

__device__ __align__(16) float g_Y0[(size_t)N0MAX*64];
__device__ __align__(16) float g_Z1[(size_t)N1MAX*64];
__device__ __align__(16) float g_YA[(size_t)N1MAX*64];
__device__ __align__(16) float g_YB[(size_t)N1MAX*64];
__device__ __align__(16) float g_Z2[(size_t)N2MAX*64];

__device__ __align__(16) int4  g_c1[N1MAX];
__device__ __align__(16) int4  g_c2[N2MAX];

__device__ __align__(16) int2  g_p0[27*TCAP];
__device__ __align__(16) int2  g_p1[27*TCAP];
__device__ __align__(16) int2  g_zp1[3*TCAP];
__device__ __align__(16) int2  g_zp2[3*TCAP];
__device__ int   g_pc0[27];
__device__ int   g_pc1[27];
__device__ int   g_zc1[3];
__device__ int   g_zc2[3];
__device__ int   g_cnt[4];          // [0]=N0  [1]=M1  [2]=M2
__device__ float g_stats[5*128];    // per BN layer: 64 sums + 64 sumsqs

// ---------------- init ----------------
__global__ void k_init(int n0) {
    size_t tid = (size_t)blockIdx.x*blockDim.x + threadIdx.x;
    size_t stride = (size_t)gridDim.x*blockDim.x;
    int4 z4 = make_int4(0,0,0,0);
    float4 f4 = make_float4(0.f,0.f,0.f,0.f);
    int4* m0 = (int4*)g_map0;
    for (size_t i = tid; i < MAP0_SZ/4; i += stride) m0[i] = z4;
    int4* m1 = (int4*)g_map1;
    for (size_t i = tid; i < MAP1_SZ/4; i += stride) m1[i] = z4;
    int4* m2 = (int4*)g_map2;
    for (size_t i = tid; i < MAP2_SZ/4; i += stride) m2[i] = z4;
    float4* z1 = (float4*)g_Z1;
    for (size_t i = tid; i < (size_t)N1MAX*16; i += stride) z1[i] = f4;
    float4* z2 = (float4*)g_Z2;
    for (size_t i = tid; i < (size_t)N2MAX*16; i += stride) z2[i] = f4;
    if (tid < 27) { g_pc0[tid] = 0; g_pc1[tid] = 0; }
    if (tid < 3)  { g_zc1[tid] = 0; g_zc2[tid] = 0; }
    if (tid < 5*128) g_stats[tid] = 0.0f;
    if (tid == 0) { g_cnt[0] = n0; g_cnt[1] = 0; g_cnt[2] = 0; g_cnt[3] = 0; }
}

// ---------------- map build / pair build ----------------
__global__ void k_map0(const int4* __restrict__ coors, int n0) {
    int i = blockIdx.x*256 + threadIdx.x;
    if (i >= n0) return;
    int4 c = coors[i];
    g_map0[((c.x*DD0 + c.y)*HH + c.z)*WW + c.w] = i + 1;
}

__global__ void k_build0(const int4* __restrict__ coors, int n0) {
    int i = blockIdx.x*256 + threadIdx.x;
    if (i >= n0) return;
    int4 c = coors[i];
    int b = c.x, z = c.y, y = c.z, x = c.w;
    #pragma unroll
    for (int dz = -1; dz <= 1; dz++)
    #pragma unroll
    for (int dy = -1; dy <= 1; dy++)
    #pragma unroll
    for (int dx = -1; dx <= 1; dx++) {
        int t = (dz+1)*9 + (dy+1)*3 + (dx+1);
        if (t == 13) continue;
        int nz = z+dz, ny = y+dy, nx = x+dx;
        if (nz < 0 || nz >= DD0 || ny < 0 || ny >= HH || nx < 0 || nx >= WW) continue;
        int j = g_map0[((b*DD0 + nz)*HH + ny)*WW + nx] - 1;
        if (j >= 0) {
            int pos = atomicAdd(&g_pc0[t], 1);
            g_p0[t*TCAP + pos] = make_int2(j, i);
        }
    }
    #pragma unroll
    for (int kz = 0; kz < 3; kz++) {
        int tt = z - kz;
        if (tt >= 0 && (tt & 1) == 0) {
            int oz = tt >> 1;
            if (oz < DD1) g_map1[((b*DD1 + oz)*HH + y)*WW + x] = 1;
        }
    }
}

// z-conv pair build (after compact): input row -> output row per kz
__global__ void k_zbuild1(const int4* __restrict__ coors, int n0) {
    int i = blockIdx.x*256 + threadIdx.x;
    if (i >= n0) return;
    int4 c = coors[i];
    #pragma unroll
    for (int kz = 0; kz < 3; kz++) {
        int tt = c.y - kz;
        if (tt >= 0 && (tt & 1) == 0) {
            int oz = tt >> 1;
            if (oz < DD1) {
                int dst = g_map1[((c.x*DD1 + oz)*HH + c.z)*WW + c.w] - 2;
                if (dst >= 0) {
                    int pos = atomicAdd(&g_zc1[kz], 1);
                    g_zp1[kz*TCAP + pos] = make_int2(i, dst);
                }
            }
        }
    }
}

__global__ void k_zbuild2() {
    int r = blockIdx.x*256 + threadIdx.x;
    if (r >= g_cnt[1]) return;
    int4 c = g_c1[r];
    #pragma unroll
    for (int kz = 0; kz < 3; kz++) {
        int tt = c.y - kz;
        if (tt >= 0 && (tt & 1) == 0) {
            int oz = tt >> 1;
            if (oz < DD2) {
                int dst = g_map2[((c.x*DD2 + oz)*HH + c.z)*WW + c.w] - 2;
                if (dst >= 0) {
                    int pos = atomicAdd(&g_zc2[kz], 1);
                    g_zp2[kz*TCAP + pos] = make_int2(r, dst);
                }
            }
        }
    }
}

__global__ void k_build1() {
    int r = blockIdx.x*256 + threadIdx.x;
    if (r >= g_cnt[1]) return;
    int4 c = g_c1[r];
    int b = c.x, z = c.y, y = c.z, x = c.w;
    #pragma unroll
    for (int dz = -1; dz <= 1; dz++)
    #pragma unroll
    for (int dy = -1; dy <= 1; dy++)
    #pragma unroll
    for (int dx = -1; dx <= 1; dx++) {
        int t = (dz+1)*9 + (dy+1)*3 + (dx+1);
        if (t == 13) continue;
        int nz = z+dz, ny = y+dy, nx = x+dx;
        if (nz < 0 || nz >= DD1 || ny < 0 || ny >= HH || nx < 0 || nx >= WW) continue;
        int j = g_map1[((b*DD1 + nz)*HH + ny)*WW + nx] - 2;
        if (j >= 0) {
            int pos = atomicAdd(&g_pc1[t], 1);
            g_p1[t*TCAP + pos] = make_int2(j, r);
        }
    }
    #pragma unroll
    for (int kz = 0; kz < 3; kz++) {
        int tt = z - kz;
        if (tt >= 0 && (tt & 1) == 0) {
            int oz = tt >> 1;
            if (oz < DD2) g_map2[((b*DD2 + oz)*HH + y)*WW + x] = 1;
        }
    }
}

// ---------------- compact marked map -> row ids + coords ----------------
__global__ void k_compact(int which) {
    int* map   = which ? g_map2 : g_map1;
    int size4  = which ? MAP2_SZ/4 : MAP1_SZ/4;
    int D      = which ? DD2 : DD1;
    int4* cout = which ? g_c2 : g_c1;
    int ci     = which ? 2 : 1;
    __shared__ int scnt, sbase;
    int gid = blockIdx.x*256 + threadIdx.x;
    if (threadIdx.x == 0) scnt = 0;
    __syncthreads();
    bool in = gid < size4;
    int4 v = make_int4(0,0,0,0);
    if (in) v = ((int4*)map)[gid];
    int vals[4] = {v.x, v.y, v.z, v.w};
    int my = (vals[0]==1) + (vals[1]==1) + (vals[2]==1) + (vals[3]==1);
    int loc = 0;
    if (my) loc = atomicAdd(&scnt, my);
    __syncthreads();
    if (threadIdx.x == 0) sbase = scnt ? atomicAdd(&g_cnt[ci], scnt) : 0;
    __syncthreads();
    if (!in) return;
    if (my) {
        int idx = sbase + loc;
        int lin = gid*4;
        int outv[4];
        #pragma unroll
        for (int q = 0; q < 4; q++) {
            if (vals[q] == 1) {
                int L = lin + q;
                int b = L / (D*HWs);
                int r = L % (D*HWs);
                int z = r / HWs;
                int rr = r % HWs;
                int y = rr / WW;
                int x = rr % WW;
                cout[idx] = make_int4(b, z, y, x);
                outv[q] = idx + 2;
                idx++;
            } else outv[q] = 0;
        }
        ((int4*)map)[gid] = make_int4(outv[0], outv[1], outv[2], outv[3]);
    }
}

// ---------------- tiled conv kernel ----------------
// MODE 0: center tap (identity row list, plain store), grid.x only
// MODE 1: pair list (grid.y = tap), atomicAdd into Y
// Tile: 64 rows x 64 channels per block of 256 threads.
// Thread t: stages row p=t&63, float4 range [g*NQ4,(g+1)*NQ4), g=t>>6.
// Compute: cq=t&15 (4 channels), rg=t>>4 (4 rows).
#define RP2 68
template<int K, int MODE>
__global__ __launch_bounds__(256) void k_conv(const float* __restrict__ X,
        const float* __restrict__ Wsrc, float* __restrict__ Y,
        const int2* __restrict__ pairsB, const int* __restrict__ pcnt, int ci) {
    extern __shared__ float sm[];
    float* sW = sm;               // K*64 floats
    float* sF = sm + K*64;        // K*RP2 floats, layout [k][row]

    constexpr int NQ4 = K/16;

    const int2* pairs = nullptr;
    int total;
    const float* Wp;
    if (MODE == 1) {
        pairs = pairsB + (size_t)blockIdx.y*TCAP;
        total = pcnt[blockIdx.y];
        Wp = Wsrc + (size_t)blockIdx.y*(K*64);
    } else {
        total = g_cnt[ci];
        Wp = Wsrc;
    }
    if ((int)blockIdx.x * 64 >= total) return;   // idle block: no weight load

    for (int i = threadIdx.x; i < K*16; i += 256)
        ((float4*)sW)[i] = ((const float4*)Wp)[i];

    const float4* Xv = (const float4*)X;
    const int p  = threadIdx.x & 63;
    const int g  = threadIdx.x >> 6;
    const int cq = threadIdx.x & 15;
    const int rg = threadIdx.x >> 4;
    const int gstride = gridDim.x * 64;

    float4 st[NQ4];
    auto prefetch = [&](int pb) {
        if (pb >= total) return;
        int pnr = total - pb; if (pnr > 64) pnr = 64;
        if (p >= pnr) {
            #pragma unroll
            for (int qi = 0; qi < NQ4; qi++) st[qi] = make_float4(0.f,0.f,0.f,0.f);
            return;
        }
        int row = (MODE == 0) ? (pb + p) : pairs[pb + p].x;
        const float4* xp = Xv + (size_t)row*(K/4) + g*NQ4;
        #pragma unroll
        for (int qi = 0; qi < NQ4; qi++) st[qi] = xp[qi];
    };

    prefetch(blockIdx.x*64);

    for (int base = blockIdx.x*64; base < total; base += gstride) {
        int nr = min(64, total - base);
        __syncthreads();
        #pragma unroll
        for (int qi = 0; qi < NQ4; qi++) {
            int q4 = g*NQ4 + qi;
            float* d = sF + (q4*4)*RP2 + p;
            d[0] = st[qi].x; d[RP2] = st[qi].y;
            d[2*RP2] = st[qi].z; d[3*RP2] = st[qi].w;
        }
        __syncthreads();
        prefetch(base + gstride);

        float4 a0 = make_float4(0.f,0.f,0.f,0.f);
        float4 a1 = a0, a2 = a0, a3 = a0;
        const float4* wv = (const float4*)sW;
        float4 wA = wv[cq];
        float4 fA = *(const float4*)(sF + rg*4);
        #pragma unroll 8
        for (int k = 0; k < K; k++) {
            float4 wB, fB;
            if (k < K-1) {
                wB = wv[(k+1)*16 + cq];
                fB = *(const float4*)(sF + (k+1)*RP2 + rg*4);
            }
            a0.x += fA.x*wA.x; a0.y += fA.x*wA.y; a0.z += fA.x*wA.z; a0.w += fA.x*wA.w;
            a1.x += fA.y*wA.x; a1.y += fA.y*wA.y; a1.z += fA.y*wA.z; a1.w += fA.y*wA.w;
            a2.x += fA.z*wA.x; a2.y += fA.z*wA.y; a2.z += fA.z*wA.z; a2.w += fA.z*wA.w;
            a3.x += fA.w*wA.x; a3.y += fA.w*wA.y; a3.z += fA.w*wA.z; a3.w += fA.w*wA.w;
            wA = wB; fA = fB;
        }
        int p0 = rg*4;
        if (MODE == 1) {
            #pragma unroll
            for (int r = 0; r < 4; r++) {
                if (p0 + r < nr) {
                    float4 a = (r==0)?a0:(r==1)?a1:(r==2)?a2:a3;
                    int dst = pairs[base + p0 + r].y;
                    float* yp = Y + (size_t)dst*64 + cq*4;
                    atomicAdd(yp+0, a.x); atomicAdd(yp+1, a.y);
                    atomicAdd(yp+2, a.z); atomicAdd(yp+3, a.w);
                }
            }
        } else {
            #pragma unroll
            for (int r = 0; r < 4; r++) {
                if (p0 + r < nr) {
                    float4 a = (r==0)?a0:(r==1)?a1:(r==2)?a2:a3;
                    ((float4*)Y)[(size_t)(base + p0 + r)*16 + cq] = a;
                }
            }
        }
    }
}

// ---------------- BN ----------------
__global__ void k_stats(const float* __restrict__ X, int ci, int layer) {
    __shared__ float ss[512];
    int cnt = g_cnt[ci];
    int c = threadIdx.x & 63, g = threadIdx.x >> 6;
    float s = 0.f, q = 0.f;
    for (int r = blockIdx.x*4 + g; r < cnt; r += gridDim.x*4) {
        float v = X[(size_t)r*64 + c];
        s += v; q += v*v;
    }
    ss[threadIdx.x] = s; ss[256 + threadIdx.x] = q;
    __syncthreads();
    if (threadIdx.x < 64) {
        s = ss[threadIdx.x] + ss[threadIdx.x+64] + ss[threadIdx.x+128] + ss[threadIdx.x+192];
        q = ss[256+threadIdx.x] + ss[320+threadIdx.x] + ss[384+threadIdx.x] + ss[448+threadIdx.x];
        atomicAdd(&g_stats[layer*128 + threadIdx.x], s);
        atomicAdd(&g_stats[layer*128 + 64 + threadIdx.x], q);
    }
}

__global__ void k_apply(float* __restrict__ X, int ci, int layer,
                        const float* __restrict__ gm, const float* __restrict__ bt) {
    __shared__ float ssc[64], sbi[64];
    int cnt = g_cnt[ci];
    float cn = fmaxf((float)cnt, 1.0f);
    if (threadIdx.x < 64) {
        int c = threadIdx.x;
        float mean = g_stats[layer*128 + c] / cn;
        float var  = g_stats[layer*128 + 64 + c] / cn - mean*mean;
        float inv  = rsqrtf(var + EPSV);
        float sc = gm[c] * inv;
        ssc[c] = sc;
        sbi[c] = bt[c] - mean*sc;
    }
    __syncthreads();
    long total = (long)cnt * 64;
    for (long e = (long)blockIdx.x*blockDim.x + threadIdx.x; e < total;
         e += (long)gridDim.x*blockDim.x) {
        int c = (int)(e & 63);
        X[e] = fmaxf(fmaf(X[e], ssc[c], sbi[c]), 0.0f);
    }
}

// ---------------- final: BN + ReLU + dense scatter (fused) ----------------
__global__ void k_out(const float* __restrict__ Z2, float* __restrict__ out,
                      const float* __restrict__ gm, const float* __restrict__ bt) {
    __shared__ float ssc[64], sbi[64];
    int cnt = g_cnt[2];
    float cn = fmaxf((float)cnt, 1.0f);
    if (threadIdx.x < 64) {
        int c = threadIdx.x;
        float mean = g_stats[512 + c] / cn;
        float var  = g_stats[512 + 64 + c] / cn - mean*mean;
        float inv  = rsqrtf(var + EPSV);
        float sc = gm[c] * inv;
        ssc[c] = sc;
        sbi[c] = bt[c] - mean*sc;
    }
    __syncthreads();
    const int tot4 = OUT_TOTAL/4;
    for (int e4 = blockIdx.x*blockDim.x + threadIdx.x; e4 < tot4;
         e4 += gridDim.x*blockDim.x) {
        int e = e4 * 4;
        int x  = e % WW;
        int t1 = e / WW;
        int y  = t1 % HH;
        int t2 = t1 / HH;
        int cz = t2 % (64*DD2);
        int b  = t2 / (64*DD2);
        int c  = cz / DD2;
        int z  = cz - c*DD2;
        float sc = ssc[c], bi = sbi[c];
        int midx = ((b*DD2 + z)*HH + y)*WW + x;
        int4 m = *reinterpret_cast<const int4*>(g_map2 + midx);
        float4 o;
        int j;
        j = m.x - 2; o.x = (j >= 0) ? fmaxf(fmaf(Z2[(size_t)j*64 + c], sc, bi), 0.f) : 0.f;
        j = m.y - 2; o.y = (j >= 0) ? fmaxf(fmaf(Z2[(size_t)j*64 + c], sc, bi), 0.f) : 0.f;
        j = m.z - 2; o.z = (j >= 0) ? fmaxf(fmaf(Z2[(size_t)j*64 + c], sc, bi), 0.f) : 0.f;
        j = m.w - 2; o.w = (j >= 0) ? fmaxf(fmaf(Z2[(size_t)j*64 + c], sc, bi), 0.f) : 0.f;
        ((float4*)out)[e4] = o;
    }
}

// ---------------- launch ----------------
extern "C" void kernel_launch(void* const* d_in, const int* in_sizes, int n_in,
                              void* d_out, int out_size) {
    const float* vox   = (const float*)d_in[0];
    const int4*  coors = (const int4*) d_in[1];
    const float* w0    = (const float*)d_in[3];
    const float* gg0   = (const float*)d_in[4];
    const float* bb0   = (const float*)d_in[5];
    const float* ws1   = (const float*)d_in[6];
    const float* ggs1  = (const float*)d_in[7];
    const float* bbs1  = (const float*)d_in[8];
    const float* w1a   = (const float*)d_in[9];
    const float* gg1a  = (const float*)d_in[10];
    const float* bb1a  = (const float*)d_in[11];
    const float* w1b   = (const float*)d_in[12];
    const float* gg1b  = (const float*)d_in[13];
    const float* bb1b  = (const float*)d_in[14];
    const float* ws2   = (const float*)d_in[15];
    const float* ggs2  = (const float*)d_in[16];
    const float* bbs2  = (const float*)d_in[17];
    float* out = (float*)d_out;
    int n0 = in_sizes[0] / 128;

    void *pY0, *pZ1, *pYA, *pYB, *pZ2, *pp0, *pp1, *pzp1, *pzp2, *ppc0, *ppc1, *pzc1, *pzc2;
    cudaGetSymbolAddress(&pY0, g_Y0);
    cudaGetSymbolAddress(&pZ1, g_Z1);
    cudaGetSymbolAddress(&pYA, g_YA);
    cudaGetSymbolAddress(&pYB, g_YB);
    cudaGetSymbolAddress(&pZ2, g_Z2);
    cudaGetSymbolAddress(&pp0, g_p0);
    cudaGetSymbolAddress(&pp1, g_p1);
    cudaGetSymbolAddress(&pzp1, g_zp1);
    cudaGetSymbolAddress(&pzp2, g_zp2);
    cudaGetSymbolAddress(&ppc0, g_pc0);
    cudaGetSymbolAddress(&ppc1, g_pc1);
    cudaGetSymbolAddress(&pzc1, g_zc1);
    cudaGetSymbolAddress(&pzc2, g_zc2);
    float* Y0 = (float*)pY0; float* Z1 = (float*)pZ1;
    float* YA = (float*)pYA; float* YB = (float*)pYB; float* Z2 = (float*)pZ2;
    const int2* P0 = (const int2*)pp0;  const int2* P1 = (const int2*)pp1;
    const int2* ZP1 = (const int2*)pzp1; const int2* ZP2 = (const int2*)pzp2;
    const int* PC0 = (const int*)ppc0;  const int* PC1 = (const int*)ppc1;
    const int* ZC1 = (const int*)pzc1;  const int* ZC2 = (const int*)pzc2;

    // dynamic smem = K*(64+RP2)*4 = K*528 bytes
    cudaFuncSetAttribute(k_conv<128,0>, cudaFuncAttributeMaxDynamicSharedMemorySize, 128*528);
    cudaFuncSetAttribute(k_conv<128,1>, cudaFuncAttributeMaxDynamicSharedMemorySize, 128*528);
    cudaFuncSetAttribute(k_conv<64,0>,  cudaFuncAttributeMaxDynamicSharedMemorySize, 64*528);
    cudaFuncSetAttribute(k_conv<64,1>,  cudaFuncAttributeMaxDynamicSharedMemorySize, 64*528);

    int gb0 = (n0 + 255) / 256;
    int gt0 = (n0 + 63) / 64;           // center tiles stage0
    int gt1 = (N1MAX + 63) / 64;        // center tiles stage1 (max, early-exit)

    k_init<<<2048, 256>>>(n0);
    k_map0<<<gb0, 256>>>(coors, n0);
    k_build0<<<gb0, 256>>>(coors, n0);

    // stage 0: subm 128->64 (center store + 26 tap pair lists)
    k_conv<128,0><<<gt0, 256, 128*528>>>(vox, w0 + 13*128*64, Y0, nullptr, nullptr, 0);
    k_conv<128,1><<<dim3(8,27), 256, 128*528>>>(vox, w0, Y0, P0, PC0, 0);
    k_stats<<<256, 256>>>(Y0, 0, 0);
    k_apply<<<512, 256>>>(Y0, 0, 0, gg0, bb0);

    // stride-z conv 1: per-kz pair lists, K=64, atomic into zeroed Z1
    k_compact<<<MAP1_SZ/4/256, 256>>>(0);
    k_zbuild1<<<gb0, 256>>>(coors, n0);
    k_conv<64,1><<<dim3(96,3), 256, 64*528>>>(Y0, ws1, Z1, ZP1, ZC1, 1);
    k_stats<<<256, 256>>>(Z1, 1, 1);
    k_apply<<<512, 256>>>(Z1, 1, 1, ggs1, bbs1);

    // subm pair build for stage 1
    k_build1<<<(N1MAX+255)/256, 256>>>();

    // subm1a
    k_conv<64,0><<<gt1, 256, 64*528>>>(Z1, w1a + 13*64*64, YA, nullptr, nullptr, 1);
    k_conv<64,1><<<dim3(16,27), 256, 64*528>>>(Z1, w1a, YA, P1, PC1, 1);
    k_stats<<<256, 256>>>(YA, 1, 2);
    k_apply<<<512, 256>>>(YA, 1, 2, gg1a, bb1a);

    // subm1b
    k_conv<64,0><<<gt1, 256, 64*528>>>(YA, w1b + 13*64*64, YB, nullptr, nullptr, 1);
    k_conv<64,1><<<dim3(16,27), 256, 64*528>>>(YA, w1b, YB, P1, PC1, 1);
    k_stats<<<256, 256>>>(YB, 1, 3);
    k_apply<<<512, 256>>>(YB, 1, 3, gg1b, bb1b);

    // stride-z conv 2: per-kz pair lists, K=64, atomic into zeroed Z2
    k_compact<<<(MAP2_SZ/4 + 255)/256, 256>>>(1);
    k_zbuild2<<<(N1MAX+255)/256, 256>>>();
    k_conv<64,1><<<dim3(96,3), 256, 64*528>>>(YB, ws2, Z2, ZP2, ZC2, 2);
    k_stats<<<256, 256>>>(Z2, 2, 4);

    // fused BN+ReLU+dense scatter
    k_out<<<2368, 256>>>(Z2, out, ggs2, bbs2);

    (void)n_in; (void)out_size;
}